// round 8
// baseline (speedup 1.0000x reference)
#include <cuda_runtime.h>
#include <cuda_fp16.h>
#include <cstdint>

#define N_NODES 4096
#define EMB 10
#define NBATCH 64
#define CI 64
#define CO 64

// ---------------- device scratch (allocation-free rule) --------------------
__device__ __half g_Ah[(size_t)N_NODES * N_NODES];   // softmax(relu(EE^T)) fp16
__device__ __half g_Xh[(size_t)N_NODES * N_NODES];   // X^T[j=b*64+c][m] fp16
__device__ float g_y1[(size_t)NBATCH * N_NODES * CI];// diffusion result [b][n][c]

// ---------------- PTX helpers ---------------------------------------------
__device__ __forceinline__ uint32_t smem_u32(const void* p) {
    uint32_t a;
    asm("{ .reg .u64 t; cvta.to.shared.u64 t, %1; cvt.u32.u64 %0, t; }" : "=r"(a) : "l"(p));
    return a;
}
__device__ __forceinline__ void cp_async16(uint32_t dst, const void* src) {
    asm volatile("cp.async.cg.shared.global [%0], [%1], 16;" :: "r"(dst), "l"(src));
}
#define CP_COMMIT()  asm volatile("cp.async.commit_group;" ::: "memory")
#define CP_WAIT(N)   asm volatile("cp.async.wait_group %0;" :: "n"(N) : "memory")

__device__ __forceinline__ void ldsm4(uint32_t* r, uint32_t addr) {
    asm volatile("ldmatrix.sync.aligned.m8n8.x4.shared.b16 {%0,%1,%2,%3}, [%4];"
        : "=r"(r[0]), "=r"(r[1]), "=r"(r[2]), "=r"(r[3]) : "r"(addr));
}
__device__ __forceinline__ void mma_f16(float* c, const uint32_t* a,
                                        uint32_t b0, uint32_t b1) {
    asm volatile("mma.sync.aligned.m16n8k16.row.col.f32.f16.f16.f32 "
        "{%0,%1,%2,%3}, {%4,%5,%6,%7}, {%8,%9}, {%0,%1,%2,%3};"
        : "+f"(c[0]), "+f"(c[1]), "+f"(c[2]), "+f"(c[3])
        : "r"(a[0]), "r"(a[1]), "r"(a[2]), "r"(a[3]), "r"(b0), "r"(b1));
}

// ---------------------------------------------------------------------------
// Kernel 1: per-row softmax of relu(E E^T) -> fp16.
// ---------------------------------------------------------------------------
__global__ __launch_bounds__(256) void k_softmax(const float* __restrict__ E) {
    const int n = blockIdx.x;
    const int tid = threadIdx.x;
    __shared__ float s_e[EMB];
    __shared__ float s_red[8];

    if (tid < EMB) s_e[tid] = E[n * EMB + tid];
    __syncthreads();
    float er[EMB];
#pragma unroll
    for (int d = 0; d < EMB; d++) er[d] = s_e[d];

    float vals[16];
    float vmax = 0.f;
#pragma unroll
    for (int j = 0; j < 16; j++) {
        const int m = tid + j * 256;
        const float* em = E + m * EMB;
        float dot = 0.f;
#pragma unroll
        for (int d = 0; d < EMB; d++) dot = fmaf(er[d], __ldg(em + d), dot);
        dot = fmaxf(dot, 0.f);
        vals[j] = dot;
        vmax = fmaxf(vmax, dot);
    }
#pragma unroll
    for (int o = 16; o; o >>= 1) vmax = fmaxf(vmax, __shfl_xor_sync(0xffffffffu, vmax, o));
    if ((tid & 31) == 0) s_red[tid >> 5] = vmax;
    __syncthreads();
    vmax = s_red[0];
#pragma unroll
    for (int w = 1; w < 8; w++) vmax = fmaxf(vmax, s_red[w]);

    float ssum = 0.f;
#pragma unroll
    for (int j = 0; j < 16; j++) {
        vals[j] = __expf(vals[j] - vmax);
        ssum += vals[j];
    }
#pragma unroll
    for (int o = 16; o; o >>= 1) ssum += __shfl_xor_sync(0xffffffffu, ssum, o);
    __syncthreads();
    if ((tid & 31) == 0) s_red[tid >> 5] = ssum;
    __syncthreads();
    ssum = 0.f;
#pragma unroll
    for (int w = 0; w < 8; w++) ssum += s_red[w];
    const float inv = 1.0f / ssum;

#pragma unroll
    for (int j = 0; j < 16; j++)
        g_Ah[(size_t)n * N_NODES + tid + j * 256] = __float2half(vals[j] * inv);
}

// ---------------------------------------------------------------------------
// Kernel 2: transpose x[b][m][c] -> X^T[j=b*64+c][m] fp16.
// ---------------------------------------------------------------------------
__global__ __launch_bounds__(256) void k_transpose(const float* __restrict__ x) {
    const int b = blockIdx.y;
    const int m0 = blockIdx.x * 64;
    const int tid = threadIdx.x;
    __shared__ float tile[64][65];

#pragma unroll
    for (int i = 0; i < 16; i++) {
        const int idx = tid + i * 256;
        const int mi = idx >> 6, c = idx & 63;
        tile[mi][c] = x[((size_t)b * N_NODES + m0 + mi) * CI + c];
    }
    __syncthreads();
#pragma unroll
    for (int i = 0; i < 16; i++) {
        const int idx = tid + i * 256;
        const int c = idx >> 6, mm = idx & 63;
        g_Xh[(size_t)(b * 64 + c) * N_NODES + m0 + mm] = __float2half(tile[mm][c]);
    }
}

// ---------------------------------------------------------------------------
// Kernel 3: y1 = A @ X via mma.sync fp16, fp32 accumulate.
// CTA tile 128x256, K-chunk 64, 2-stage cp.async, 8 warps (2Mx4N), warp 64x64.
// Row pad 144B -> conflict-free ldmatrix.
// ---------------------------------------------------------------------------
#define KC 64
#define ROWB 144                      // 64 fp16 = 128B data + 16B pad
#define TILEA_B (128 * ROWB)          // 18432 B
#define TILEB_B (256 * ROWB)          // 36864 B
#define STAGE_B (TILEA_B + TILEB_B)   // 55296 B
#define SMEM_MMA (2 * STAGE_B)        // 110592 B
#define NT (N_NODES / KC)             // 64 chunks

__global__ __launch_bounds__(256, 1) void k_mma() {
    extern __shared__ __align__(128) char smem[];
    const uint32_t sb = smem_u32(smem);
    const int tid = threadIdx.x;
    const int wid = tid >> 5;
    const int lane = tid & 31;
    const int wm = wid >> 2;          // 0..1  (M: 64 rows each)
    const int wn = wid & 3;           // 0..3  (N: 64 cols each)
    const int n0 = blockIdx.y * 128;
    const int j0 = blockIdx.x * 256;

    // global load: A 4 segs/thread, B 8 segs/thread (16B each)
    int garow[4], gaseg[4];
    uint32_t sdstA[4];
#pragma unroll
    for (int i = 0; i < 4; i++) {
        const int s = tid + i * 256;      // 0..1023
        garow[i] = s >> 3;                // 0..127
        gaseg[i] = s & 7;
        sdstA[i] = (uint32_t)(garow[i] * ROWB + gaseg[i] * 16);
    }
    int gbrow[8], gbseg[8];
    uint32_t sdstB[8];
#pragma unroll
    for (int i = 0; i < 8; i++) {
        const int s = tid + i * 256;      // 0..2047
        gbrow[i] = s >> 3;                // 0..255
        gbseg[i] = s & 7;
        sdstB[i] = (uint32_t)(gbrow[i] * ROWB + gbseg[i] * 16);
    }

    // ldmatrix source offsets
    uint32_t offA[4], offB[4];
#pragma unroll
    for (int mb = 0; mb < 4; mb++)
        offA[mb] = (uint32_t)((wm * 64 + mb * 16 + (lane & 15)) * ROWB + (lane >> 4) * 16);
#pragma unroll
    for (int nb = 0; nb < 4; nb++)
        offB[nb] = (uint32_t)((wn * 64 + nb * 16 + (lane & 15)) * ROWB + (lane >> 4) * 16);

    float acc[4][8][4];
#pragma unroll
    for (int mb = 0; mb < 4; mb++)
#pragma unroll
        for (int nb = 0; nb < 8; nb++)
#pragma unroll
            for (int q = 0; q < 4; q++) acc[mb][nb][q] = 0.f;

    // prologue: chunk 0 -> stage 0
    {
#pragma unroll
        for (int i = 0; i < 4; i++)
            cp_async16(sb + sdstA[i], g_Ah + (size_t)(n0 + garow[i]) * N_NODES + gaseg[i] * 8);
#pragma unroll
        for (int i = 0; i < 8; i++)
            cp_async16(sb + TILEA_B + sdstB[i], g_Xh + (size_t)(j0 + gbrow[i]) * N_NODES + gbseg[i] * 8);
        CP_COMMIT();
    }

    for (int t = 0; t < NT; t++) {
        const int s = t & 1;
        if (t + 1 < NT) {
            const uint32_t st = sb + (s ^ 1) * STAGE_B;
            const int m0 = (t + 1) * KC;
#pragma unroll
            for (int i = 0; i < 4; i++)
                cp_async16(st + sdstA[i], g_Ah + (size_t)(n0 + garow[i]) * N_NODES + m0 + gaseg[i] * 8);
#pragma unroll
            for (int i = 0; i < 8; i++)
                cp_async16(st + TILEA_B + sdstB[i], g_Xh + (size_t)(j0 + gbrow[i]) * N_NODES + m0 + gbseg[i] * 8);
            CP_COMMIT();
            CP_WAIT(1);
        } else {
            CP_WAIT(0);
        }
        __syncthreads();

        const uint32_t bA = sb + s * STAGE_B;
        const uint32_t bB = bA + TILEA_B;
#pragma unroll
        for (int ks = 0; ks < 4; ks++) {
            const uint32_t ko = ks * 32;   // 16 fp16 = 32 bytes
            uint32_t ah[4][4];
#pragma unroll
            for (int mb = 0; mb < 4; mb++) ldsm4(ah[mb], bA + offA[mb] + ko);
#pragma unroll
            for (int nb = 0; nb < 4; nb++) {
                uint32_t bh[4];
                ldsm4(bh, bB + offB[nb] + ko);
#pragma unroll
                for (int mb = 0; mb < 4; mb++) {
                    mma_f16(acc[mb][nb * 2 + 0], ah[mb], bh[0], bh[2]);
                    mma_f16(acc[mb][nb * 2 + 1], ah[mb], bh[1], bh[3]);
                }
            }
        }
        __syncthreads();
    }

    // epilogue: write y1[b][n][c]; each warp's 64-col span lies in ONE batch b.
    const int b = (j0 + wn * 64) >> 6;
#pragma unroll
    for (int mb = 0; mb < 4; mb++) {
        const int nrow = n0 + wm * 64 + mb * 16 + (lane >> 2);
#pragma unroll
        for (int nb = 0; nb < 8; nb++) {
            const int c = nb * 8 + (lane & 3) * 2;
            float* d0 = &g_y1[((size_t)b * N_NODES + nrow) * CI + c];
            float* d1 = &g_y1[((size_t)b * N_NODES + nrow + 8) * CI + c];
            float2 v0 = {acc[mb][nb][0], acc[mb][nb][1]};
            float2 v1 = {acc[mb][nb][2], acc[mb][nb][3]};
            *(float2*)d0 = v0;
            *(float2*)d1 = v1;
        }
    }
}

// ---------------------------------------------------------------------------
// Kernel 4: per-node weights + final per-node GEMM, 4-batch register blocking.
// ---------------------------------------------------------------------------
#define SXT_OFF  8192                 // floats: sW occupies [0, 8192)
#define SYT_OFF  (SXT_OFF + 64 * 68)
#define SB_OFF   (SYT_OFF + 64 * 68)
#define SE_OFF   (SB_OFF + 64)
#define KOUT_SMEM ((SE_OFF + 16) * 4)

__global__ __launch_bounds__(256) void k_out(const float* __restrict__ E,
                                             const float* __restrict__ Wp,
                                             const float* __restrict__ bp,
                                             const float* __restrict__ x,
                                             float* __restrict__ out) {
    extern __shared__ float dsm[];
    const int n = blockIdx.x;
    const int tid = threadIdx.x;

    if (tid < EMB) dsm[SE_OFF + tid] = E[n * EMB + tid];
    __syncthreads();
    float e[EMB];
#pragma unroll
    for (int d = 0; d < EMB; d++) e[d] = dsm[SE_OFF + d];

#pragma unroll 8
    for (int u = 0; u < 32; u++) {
        const int idx = tid + u * 256;
        float acc = 0.f;
#pragma unroll
        for (int d = 0; d < EMB; d++) acc = fmaf(e[d], __ldg(Wp + d * 8192 + idx), acc);
        dsm[idx] = acc;
    }
    if (tid < 64) {
        float acc = 0.f;
#pragma unroll
        for (int d = 0; d < EMB; d++) acc = fmaf(e[d], bp[d * 64 + tid], acc);
        dsm[SB_OFF + tid] = acc;
    }

#pragma unroll
    for (int u = 0; u < 16; u++) {
        const int idx = tid + u * 256;
        const int b = idx >> 6, i = idx & 63;
        dsm[SXT_OFF + i * 68 + b] = x[((size_t)b * N_NODES + n) * CI + i];
        dsm[SYT_OFF + i * 68 + b] = g_y1[((size_t)b * N_NODES + n) * CI + i];
    }
    __syncthreads();

    const int og = tid & 15;
    const int bq = tid >> 4;

    float acc[4][4];
    const float4 bias = *(const float4*)&dsm[SB_OFF + og * 4];
#pragma unroll
    for (int bb = 0; bb < 4; bb++) {
        acc[bb][0] = bias.x; acc[bb][1] = bias.y; acc[bb][2] = bias.z; acc[bb][3] = bias.w;
    }

#pragma unroll 8
    for (int i = 0; i < 64; i++) {
        const float4 w0 = *(const float4*)&dsm[i * 64 + og * 4];
        const float4 w1 = *(const float4*)&dsm[4096 + i * 64 + og * 4];
        const float4 xv = *(const float4*)&dsm[SXT_OFF + i * 68 + bq * 4];
        const float4 yv = *(const float4*)&dsm[SYT_OFF + i * 68 + bq * 4];
        const float xr[4] = {xv.x, xv.y, xv.z, xv.w};
        const float yr[4] = {yv.x, yv.y, yv.z, yv.w};
#pragma unroll
        for (int bb = 0; bb < 4; bb++) {
            acc[bb][0] = fmaf(xr[bb], w0.x, fmaf(yr[bb], w1.x, acc[bb][0]));
            acc[bb][1] = fmaf(xr[bb], w0.y, fmaf(yr[bb], w1.y, acc[bb][1]));
            acc[bb][2] = fmaf(xr[bb], w0.z, fmaf(yr[bb], w1.z, acc[bb][2]));
            acc[bb][3] = fmaf(xr[bb], w0.w, fmaf(yr[bb], w1.w, acc[bb][3]));
        }
    }

#pragma unroll
    for (int bb = 0; bb < 4; bb++) {
        float4 v = {acc[bb][0], acc[bb][1], acc[bb][2], acc[bb][3]};
        *(float4*)&out[((size_t)(bq * 4 + bb) * N_NODES + n) * CO + og * 4] = v;
    }
}

// ---------------------------------------------------------------------------
extern "C" void kernel_launch(void* const* d_in, const int* in_sizes, int n_in,
                              void* d_out, int out_size) {
    const float* x  = (const float*)d_in[0];
    const float* E  = (const float*)d_in[1];
    const float* Wp = (const float*)d_in[2];
    const float* bp = (const float*)d_in[3];
    float* out = (float*)d_out;

    cudaFuncSetAttribute(k_mma, cudaFuncAttributeMaxDynamicSharedMemorySize, SMEM_MMA);
    cudaFuncSetAttribute(k_out, cudaFuncAttributeMaxDynamicSharedMemorySize, KOUT_SMEM);

    k_softmax<<<N_NODES, 256>>>(E);
    dim3 gT(N_NODES / 64, NBATCH);
    k_transpose<<<gT, 256>>>(x);
    dim3 gM(N_NODES / 256, N_NODES / 128);
    k_mma<<<gM, 256, SMEM_MMA>>>();
    k_out<<<N_NODES, 256, KOUT_SMEM>>>(E, Wp, bp, x, out);
}

// round 11
// speedup vs baseline: 1.3303x; 1.3303x over previous
#include <cuda_runtime.h>
#include <cuda_fp16.h>
#include <cstdint>

#define N_NODES 4096
#define EMB 10
#define NBATCH 64
#define CI 64
#define CO 64

// ---------------- device scratch (allocation-free rule) --------------------
__device__ __half g_Ah[(size_t)N_NODES * N_NODES];    // softmax(relu(EE^T)) fp16
__device__ __half g_Xh[(size_t)N_NODES * N_NODES];    // X^T[j=b*64+c][m] fp16
__device__ __half g_xh16[(size_t)NBATCH * N_NODES * CI]; // x fp16 [b][n][i]
__device__ __half g_y1h[(size_t)NBATCH * N_NODES * CI];  // y1 fp16 [b][n][c]
__device__ float  g_Wpp[(size_t)EMB * 8192];          // permuted pool [d][o*128+k*64+i]
__device__ __half g_Wt[(size_t)N_NODES * 8192];       // per-node W^T fp16 [n][o][ki]

// ---------------- PTX helpers ---------------------------------------------
__device__ __forceinline__ uint32_t smem_u32(const void* p) {
    uint32_t a;
    asm("{ .reg .u64 t; cvta.to.shared.u64 t, %1; cvt.u32.u64 %0, t; }" : "=r"(a) : "l"(p));
    return a;
}
__device__ __forceinline__ void cp_async16(uint32_t dst, const void* src) {
    asm volatile("cp.async.cg.shared.global [%0], [%1], 16;" :: "r"(dst), "l"(src));
}
#define CP_COMMIT()  asm volatile("cp.async.commit_group;" ::: "memory")
#define CP_WAIT(N)   asm volatile("cp.async.wait_group %0;" :: "n"(N) : "memory")

__device__ __forceinline__ void ldsm4(uint32_t* r, uint32_t addr) {
    asm volatile("ldmatrix.sync.aligned.m8n8.x4.shared.b16 {%0,%1,%2,%3}, [%4];"
        : "=r"(r[0]), "=r"(r[1]), "=r"(r[2]), "=r"(r[3]) : "r"(addr));
}
__device__ __forceinline__ void mma_f16(float* c, const uint32_t* a,
                                        uint32_t b0, uint32_t b1) {
    asm volatile("mma.sync.aligned.m16n8k16.row.col.f32.f16.f16.f32 "
        "{%0,%1,%2,%3}, {%4,%5,%6,%7}, {%8,%9}, {%0,%1,%2,%3};"
        : "+f"(c[0]), "+f"(c[1]), "+f"(c[2]), "+f"(c[3])
        : "r"(a[0]), "r"(a[1]), "r"(a[2]), "r"(a[3]), "r"(b0), "r"(b1));
}
__device__ __forceinline__ uint32_t h2_bits(float lo, float hi) {
    __half2 h = __floats2half2_rn(lo, hi);
    uint32_t u;
    memcpy(&u, &h, 4);
    return u;
}

// ---------------------------------------------------------------------------
// Kernel 1: per-row softmax of relu(E E^T) -> fp16.
// ---------------------------------------------------------------------------
__global__ __launch_bounds__(256) void k_softmax(const float* __restrict__ E) {
    const int n = blockIdx.x;
    const int tid = threadIdx.x;
    __shared__ float s_e[EMB];
    __shared__ float s_red[8];

    if (tid < EMB) s_e[tid] = E[n * EMB + tid];
    __syncthreads();
    float er[EMB];
#pragma unroll
    for (int d = 0; d < EMB; d++) er[d] = s_e[d];

    float vals[16];
    float vmax = 0.f;
#pragma unroll
    for (int j = 0; j < 16; j++) {
        const int m = tid + j * 256;
        const float* em = E + m * EMB;
        float dot = 0.f;
#pragma unroll
        for (int d = 0; d < EMB; d++) dot = fmaf(er[d], __ldg(em + d), dot);
        dot = fmaxf(dot, 0.f);
        vals[j] = dot;
        vmax = fmaxf(vmax, dot);
    }
#pragma unroll
    for (int o = 16; o; o >>= 1) vmax = fmaxf(vmax, __shfl_xor_sync(0xffffffffu, vmax, o));
    if ((tid & 31) == 0) s_red[tid >> 5] = vmax;
    __syncthreads();
    vmax = s_red[0];
#pragma unroll
    for (int w = 1; w < 8; w++) vmax = fmaxf(vmax, s_red[w]);

    float ssum = 0.f;
#pragma unroll
    for (int j = 0; j < 16; j++) {
        vals[j] = __expf(vals[j] - vmax);
        ssum += vals[j];
    }
#pragma unroll
    for (int o = 16; o; o >>= 1) ssum += __shfl_xor_sync(0xffffffffu, ssum, o);
    __syncthreads();
    if ((tid & 31) == 0) s_red[tid >> 5] = ssum;
    __syncthreads();
    ssum = 0.f;
#pragma unroll
    for (int w = 0; w < 8; w++) ssum += s_red[w];
    const float inv = 1.0f / ssum;

#pragma unroll
    for (int j = 0; j < 16; j++)
        g_Ah[(size_t)n * N_NODES + tid + j * 256] = __float2half(vals[j] * inv);
}

// ---------------------------------------------------------------------------
// Kernel 2: transpose x -> X^T fp16 for the diffusion GEMM; also x fp16 [b][n][i].
// ---------------------------------------------------------------------------
__global__ __launch_bounds__(256) void k_transpose(const float* __restrict__ x) {
    const int b = blockIdx.y;
    const int m0 = blockIdx.x * 64;
    const int tid = threadIdx.x;
    __shared__ float tile[64][65];

#pragma unroll
    for (int i = 0; i < 16; i++) {
        const int idx = tid + i * 256;
        const int mi = idx >> 6, c = idx & 63;
        const float v = x[((size_t)b * N_NODES + m0 + mi) * CI + c];
        tile[mi][c] = v;
        g_xh16[((size_t)b * N_NODES + m0 + mi) * CI + c] = __float2half(v);
    }
    __syncthreads();
#pragma unroll
    for (int i = 0; i < 16; i++) {
        const int idx = tid + i * 256;
        const int c = idx >> 6, mm = idx & 63;
        g_Xh[(size_t)(b * 64 + c) * N_NODES + m0 + mm] = __float2half(tile[mm][c]);
    }
}

// ---------------------------------------------------------------------------
// Kernel 2b: permute weights_pool [d][k][i][o] -> Wpp[d][o*128 + k*64 + i] f32.
// ---------------------------------------------------------------------------
__global__ __launch_bounds__(256) void k_perm(const float* __restrict__ Wp) {
    const int idx = blockIdx.x * 256 + threadIdx.x;  // < 81920
    const int d = idx >> 13;
    const int r = idx & 8191;        // o*128 + k*64 + i
    const int o = r >> 7;
    const int k = (r >> 6) & 1;
    const int i = r & 63;
    g_Wpp[idx] = Wp[d * 8192 + k * 4096 + i * 64 + o];
}

// ---------------------------------------------------------------------------
// Kernel 2c: Wt[n][p] = sum_d E[n,d] * Wpp[d][p], fp16 out.
// CTA: 32-node block x 1024-p block. Wpp slice held in registers, reused 32x.
// ---------------------------------------------------------------------------
__global__ __launch_bounds__(256) void k_wgen(const float* __restrict__ E) {
    const int p0 = blockIdx.x * 1024;
    const int n0 = blockIdx.y * 32;
    const int tid = threadIdx.x;
    __shared__ float sE[32][EMB];

    for (int s = tid; s < 32 * EMB; s += 256)
        sE[s / EMB][s % EMB] = E[(n0 + s / EMB) * EMB + s % EMB];

    const int p = p0 + tid * 4;
    float4 w[EMB];
#pragma unroll
    for (int d = 0; d < EMB; d++) w[d] = *(const float4*)&g_Wpp[(size_t)d * 8192 + p];
    __syncthreads();

#pragma unroll 4
    for (int nn = 0; nn < 32; nn++) {
        float4 acc = {0.f, 0.f, 0.f, 0.f};
#pragma unroll
        for (int d = 0; d < EMB; d++) {
            const float e = sE[nn][d];
            acc.x = fmaf(e, w[d].x, acc.x);
            acc.y = fmaf(e, w[d].y, acc.y);
            acc.z = fmaf(e, w[d].z, acc.z);
            acc.w = fmaf(e, w[d].w, acc.w);
        }
        uint2 pk;
        pk.x = h2_bits(acc.x, acc.y);
        pk.y = h2_bits(acc.z, acc.w);
        *(uint2*)&g_Wt[(size_t)(n0 + nn) * 8192 + p] = pk;
    }
}

// ---------------------------------------------------------------------------
// Kernel 3: y1 = A @ X via mma.sync fp16 (128x128, KC=64, 2 CTA/SM).
// Epilogue writes y1 as fp16 [b][n][c].
// ---------------------------------------------------------------------------
#define KC 64
#define ROWB 144
#define TILE_B (128 * ROWB)
#define STAGE_B (2 * TILE_B)
#define SMEM_MMA (2 * STAGE_B)        // 73728 B
#define NT (N_NODES / KC)

__global__ __launch_bounds__(256, 2) void k_mma() {
    extern __shared__ __align__(128) char smem[];
    const uint32_t sb = smem_u32(smem);
    const int tid = threadIdx.x;
    const int wid = tid >> 5;
    const int lane = tid & 31;
    const int wm = wid >> 1;
    const int wn = wid & 1;
    const int n0 = blockIdx.y * 128;
    const int j0 = blockIdx.x * 128;

    int grow[4], gseg[4];
    uint32_t sdst[4];
#pragma unroll
    for (int i = 0; i < 4; i++) {
        const int s = tid + i * 256;
        grow[i] = s >> 3;
        gseg[i] = s & 7;
        sdst[i] = (uint32_t)(grow[i] * ROWB + gseg[i] * 16);
    }

    uint32_t offA[2], offB[4];
#pragma unroll
    for (int mb = 0; mb < 2; mb++)
        offA[mb] = (uint32_t)((wm * 32 + mb * 16 + (lane & 15)) * ROWB + (lane >> 4) * 16);
#pragma unroll
    for (int nb = 0; nb < 4; nb++)
        offB[nb] = (uint32_t)((wn * 64 + nb * 16 + (lane & 15)) * ROWB + (lane >> 4) * 16);

    float acc[2][8][4];
#pragma unroll
    for (int mb = 0; mb < 2; mb++)
#pragma unroll
        for (int nb = 0; nb < 8; nb++)
#pragma unroll
            for (int q = 0; q < 4; q++) acc[mb][nb][q] = 0.f;

    {
#pragma unroll
        for (int i = 0; i < 4; i++) {
            cp_async16(sb + sdst[i],          g_Ah + (size_t)(n0 + grow[i]) * N_NODES + gseg[i] * 8);
            cp_async16(sb + TILE_B + sdst[i], g_Xh + (size_t)(j0 + grow[i]) * N_NODES + gseg[i] * 8);
        }
        CP_COMMIT();
    }

    for (int t = 0; t < NT; t++) {
        const int s = t & 1;
        if (t + 1 < NT) {
            const uint32_t st = sb + (s ^ 1) * STAGE_B;
            const int m0 = (t + 1) * KC;
#pragma unroll
            for (int i = 0; i < 4; i++) {
                cp_async16(st + sdst[i],          g_Ah + (size_t)(n0 + grow[i]) * N_NODES + m0 + gseg[i] * 8);
                cp_async16(st + TILE_B + sdst[i], g_Xh + (size_t)(j0 + grow[i]) * N_NODES + m0 + gseg[i] * 8);
            }
            CP_COMMIT();
            CP_WAIT(1);
        } else {
            CP_WAIT(0);
        }
        __syncthreads();

        const uint32_t bA = sb + s * STAGE_B;
        const uint32_t bB = bA + TILE_B;
#pragma unroll
        for (int ks = 0; ks < 4; ks++) {
            const uint32_t ko = ks * 32;
            uint32_t ah[2][4];
#pragma unroll
            for (int mb = 0; mb < 2; mb++) ldsm4(ah[mb], bA + offA[mb] + ko);
#pragma unroll
            for (int nb = 0; nb < 4; nb++) {
                uint32_t bh[4];
                ldsm4(bh, bB + offB[nb] + ko);
#pragma unroll
                for (int mb = 0; mb < 2; mb++) {
                    mma_f16(acc[mb][nb * 2 + 0], ah[mb], bh[0], bh[2]);
                    mma_f16(acc[mb][nb * 2 + 1], ah[mb], bh[1], bh[3]);
                }
            }
        }
        __syncthreads();
    }

    const int b = (j0 + wn * 64) >> 6;
#pragma unroll
    for (int mb = 0; mb < 2; mb++) {
        const int nrow = n0 + wm * 32 + mb * 16 + (lane >> 2);
#pragma unroll
        for (int nb = 0; nb < 8; nb++) {
            const int c = nb * 8 + (lane & 3) * 2;
            const uint32_t v0 = h2_bits(acc[mb][nb][0], acc[mb][nb][1]);
            const uint32_t v1 = h2_bits(acc[mb][nb][2], acc[mb][nb][3]);
            *(uint32_t*)&g_y1h[((size_t)b * N_NODES + nrow) * CI + c] = v0;
            *(uint32_t*)&g_y1h[((size_t)b * N_NODES + nrow + 8) * CI + c] = v1;
        }
    }
}

// ---------------------------------------------------------------------------
// Kernel 4: out[b,o] = A[b,ki] * Wt[o,ki] + bias, per node, tensor cores.
// A = [x fp16 | y1 fp16] (64x128), Wt fp16 (64x128). 128 threads, 4 warps.
// ---------------------------------------------------------------------------
#define KO_PITCH 272                   // bytes per smem row (136 halfs)

__global__ __launch_bounds__(128) void k_out(const float* __restrict__ E,
                                             const float* __restrict__ bp,
                                             float* __restrict__ out) {
    __shared__ __align__(16) char sAraw[64 * KO_PITCH];
    __shared__ __align__(16) char sWraw[64 * KO_PITCH];
    __shared__ float sbias[64];
    __shared__ float sE[EMB];

    const int n = blockIdx.x;
    const int tid = threadIdx.x;
    const int wid = tid >> 5;
    const int lane = tid & 31;
    const uint32_t aA = smem_u32(sAraw);
    const uint32_t aW = smem_u32(sWraw);

    // W tile: 64 rows x 256B = 1024 x 16B segments
#pragma unroll
    for (int i = 0; i < 8; i++) {
        const int s = tid + i * 128;          // 0..1023
        const int row = s >> 4, seg = s & 15;
        cp_async16(aW + row * KO_PITCH + seg * 16,
                   g_Wt + (size_t)n * 8192 + row * 128 + seg * 8);
    }
    // A tile: 64 rows; x fills bytes [0,128), y1 fills [128,256)
#pragma unroll
    for (int i = 0; i < 4; i++) {
        const int s = tid + i * 128;          // 0..511
        const int b = s >> 3, seg = s & 7;
        cp_async16(aA + b * KO_PITCH + seg * 16,
                   g_xh16 + ((size_t)b * N_NODES + n) * CI + seg * 8);
        cp_async16(aA + b * KO_PITCH + 128 + seg * 16,
                   g_y1h + ((size_t)b * N_NODES + n) * CI + seg * 8);
    }
    CP_COMMIT();

    if (tid < EMB) sE[tid] = E[n * EMB + tid];
    __syncthreads();
    if (tid < 64) {
        float acc = 0.f;
#pragma unroll
        for (int d = 0; d < EMB; d++) acc = fmaf(sE[d], bp[d * 64 + tid], acc);
        sbias[tid] = acc;
    }
    CP_WAIT(0);
    __syncthreads();

    const uint32_t offA = (uint32_t)((wid * 16 + (lane & 15)) * KO_PITCH + (lane >> 4) * 16);
    uint32_t offB[4];
#pragma unroll
    for (int nb = 0; nb < 4; nb++)
        offB[nb] = (uint32_t)((nb * 16 + (lane & 15)) * KO_PITCH + (lane >> 4) * 16);

    float acc[8][4];
#pragma unroll
    for (int nb = 0; nb < 8; nb++)
#pragma unroll
        for (int q = 0; q < 4; q++) acc[nb][q] = 0.f;

#pragma unroll
    for (int ks = 0; ks < 8; ks++) {
        const uint32_t ko = ks * 32;
        uint32_t ah[4];
        ldsm4(ah, aA + offA + ko);
#pragma unroll
        for (int nb = 0; nb < 4; nb++) {
            uint32_t bh[4];
            ldsm4(bh, aW + offB[nb] + ko);
            mma_f16(acc[nb * 2 + 0], ah, bh[0], bh[2]);
            mma_f16(acc[nb * 2 + 1], ah, bh[1], bh[3]);
        }
    }

    const int brow = wid * 16 + (lane >> 2);
#pragma unroll
    for (int nb = 0; nb < 8; nb++) {
        const int o = nb * 8 + (lane & 3) * 2;
        const float2 bias = *(const float2*)&sbias[o];
        float2 v0 = {acc[nb][0] + bias.x, acc[nb][1] + bias.y};
        float2 v1 = {acc[nb][2] + bias.x, acc[nb][3] + bias.y};
        *(float2*)&out[((size_t)brow * N_NODES + n) * CO + o] = v0;
        *(float2*)&out[((size_t)(brow + 8) * N_NODES + n) * CO + o] = v1;
    }
}

// ---------------------------------------------------------------------------
extern "C" void kernel_launch(void* const* d_in, const int* in_sizes, int n_in,
                              void* d_out, int out_size) {
    const float* x  = (const float*)d_in[0];
    const float* E  = (const float*)d_in[1];
    const float* Wp = (const float*)d_in[2];
    const float* bp = (const float*)d_in[3];
    float* out = (float*)d_out;

    cudaFuncSetAttribute(k_mma, cudaFuncAttributeMaxDynamicSharedMemorySize, SMEM_MMA);

    k_softmax<<<N_NODES, 256>>>(E);
    dim3 gT(N_NODES / 64, NBATCH);
    k_transpose<<<gT, 256>>>(x);
    k_perm<<<(EMB * 8192) / 256, 256>>>(Wp);
    dim3 gW(8192 / 1024, N_NODES / 32);
    k_wgen<<<gW, 256>>>(E);
    dim3 gM(N_NODES / 128, N_NODES / 128);
    k_mma<<<gM, 256, SMEM_MMA>>>();
    k_out<<<N_NODES, 128>>>(E, bp, out);
}

// round 13
// speedup vs baseline: 1.4046x; 1.0558x over previous
#include <cuda_runtime.h>
#include <cuda_fp16.h>
#include <cstdint>

#define N_NODES 4096
#define EMB 10
#define NBATCH 64
#define CI 64
#define CO 64

// ---------------- device scratch (allocation-free rule) --------------------
__device__ __half g_Ah[(size_t)N_NODES * N_NODES];    // softmax(relu(EE^T)) fp16
__device__ __half g_Xh[(size_t)N_NODES * N_NODES];    // X^T[j=b*64+c][m] fp16
__device__ __half g_xh16[(size_t)NBATCH * N_NODES * CI]; // x fp16 [b][n][i]
__device__ __half g_y1h[(size_t)NBATCH * N_NODES * CI];  // y1 fp16 [b][n][c]
__device__ float  g_Wpp[(size_t)EMB * 8192];          // permuted pool [d][o*128+k*64+i]
__device__ __half g_Wt[(size_t)N_NODES * 8192];       // per-node W^T fp16 [n][o][ki]

// ---------------- PTX helpers ---------------------------------------------
__device__ __forceinline__ uint32_t smem_u32(const void* p) {
    uint32_t a;
    asm("{ .reg .u64 t; cvta.to.shared.u64 t, %1; cvt.u32.u64 %0, t; }" : "=r"(a) : "l"(p));
    return a;
}
__device__ __forceinline__ void cp_async16(uint32_t dst, const void* src) {
    asm volatile("cp.async.cg.shared.global [%0], [%1], 16;" :: "r"(dst), "l"(src));
}
#define CP_COMMIT()  asm volatile("cp.async.commit_group;" ::: "memory")
#define CP_WAIT(N)   asm volatile("cp.async.wait_group %0;" :: "n"(N) : "memory")

__device__ __forceinline__ void ldsm4(uint32_t* r, uint32_t addr) {
    asm volatile("ldmatrix.sync.aligned.m8n8.x4.shared.b16 {%0,%1,%2,%3}, [%4];"
        : "=r"(r[0]), "=r"(r[1]), "=r"(r[2]), "=r"(r[3]) : "r"(addr));
}
__device__ __forceinline__ void mma_f16(float* c, const uint32_t* a,
                                        uint32_t b0, uint32_t b1) {
    asm volatile("mma.sync.aligned.m16n8k16.row.col.f32.f16.f16.f32 "
        "{%0,%1,%2,%3}, {%4,%5,%6,%7}, {%8,%9}, {%0,%1,%2,%3};"
        : "+f"(c[0]), "+f"(c[1]), "+f"(c[2]), "+f"(c[3])
        : "r"(a[0]), "r"(a[1]), "r"(a[2]), "r"(a[3]), "r"(b0), "r"(b1));
}
__device__ __forceinline__ uint32_t h2_bits(float lo, float hi) {
    __half2 h = __floats2half2_rn(lo, hi);
    uint32_t u;
    memcpy(&u, &h, 4);
    return u;
}

// ---------------------------------------------------------------------------
// Kernel 1: softmax(relu(E E^T)) -> fp16, 8 rows per CTA, two passes.
// No max subtraction: dot <= ~40 so exp() stays in fp32 range.
// ---------------------------------------------------------------------------
#define SM_ROWS 8

__global__ __launch_bounds__(256) void k_softmax(const float* __restrict__ E) {
    const int r0 = blockIdx.x * SM_ROWS;
    const int tid = threadIdx.x;
    __shared__ float sER[SM_ROWS * EMB];
    __shared__ float sred[8][SM_ROWS];
    __shared__ float sinv[SM_ROWS];

    if (tid < SM_ROWS * EMB) sER[tid] = E[r0 * EMB + tid];
    __syncthreads();

    float er[SM_ROWS][EMB];
#pragma unroll
    for (int r = 0; r < SM_ROWS; r++)
#pragma unroll
        for (int d = 0; d < EMB; d++) er[r][d] = sER[r * EMB + d];

    // pass 1: row sums of exp(relu(dot))
    float ssum[SM_ROWS];
#pragma unroll
    for (int r = 0; r < SM_ROWS; r++) ssum[r] = 0.f;

    for (int it = 0; it < 16; it++) {
        const int m = tid + it * 256;
        float em[EMB];
#pragma unroll
        for (int d = 0; d < EMB; d++) em[d] = __ldg(E + m * EMB + d);
#pragma unroll
        for (int r = 0; r < SM_ROWS; r++) {
            float dot = 0.f;
#pragma unroll
            for (int d = 0; d < EMB; d++) dot = fmaf(em[d], er[r][d], dot);
            ssum[r] += __expf(fmaxf(dot, 0.f));
        }
    }
#pragma unroll
    for (int r = 0; r < SM_ROWS; r++)
#pragma unroll
        for (int o = 16; o; o >>= 1) ssum[r] += __shfl_xor_sync(0xffffffffu, ssum[r], o);
    if ((tid & 31) == 0) {
#pragma unroll
        for (int r = 0; r < SM_ROWS; r++) sred[tid >> 5][r] = ssum[r];
    }
    __syncthreads();
    if (tid < SM_ROWS) {
        float s = 0.f;
#pragma unroll
        for (int w = 0; w < 8; w++) s += sred[w][tid];
        sinv[tid] = 1.0f / s;
    }
    __syncthreads();
    float inv[SM_ROWS];
#pragma unroll
    for (int r = 0; r < SM_ROWS; r++) inv[r] = sinv[r];

    // pass 2: recompute (E cached in L1) and write normalized fp16
    for (int it = 0; it < 16; it++) {
        const int m = tid + it * 256;
        float em[EMB];
#pragma unroll
        for (int d = 0; d < EMB; d++) em[d] = __ldg(E + m * EMB + d);
#pragma unroll
        for (int r = 0; r < SM_ROWS; r++) {
            float dot = 0.f;
#pragma unroll
            for (int d = 0; d < EMB; d++) dot = fmaf(em[d], er[r][d], dot);
            const float v = __expf(fmaxf(dot, 0.f)) * inv[r];
            g_Ah[(size_t)(r0 + r) * N_NODES + m] = __float2half(v);
        }
    }
}

// ---------------------------------------------------------------------------
// Kernel 2: transpose x -> X^T fp16 for the diffusion GEMM; also x fp16 [b][n][i].
// ---------------------------------------------------------------------------
__global__ __launch_bounds__(256) void k_transpose(const float* __restrict__ x) {
    const int b = blockIdx.y;
    const int m0 = blockIdx.x * 64;
    const int tid = threadIdx.x;
    __shared__ float tile[64][65];

#pragma unroll
    for (int i = 0; i < 16; i++) {
        const int idx = tid + i * 256;
        const int mi = idx >> 6, c = idx & 63;
        const float v = x[((size_t)b * N_NODES + m0 + mi) * CI + c];
        tile[mi][c] = v;
        g_xh16[((size_t)b * N_NODES + m0 + mi) * CI + c] = __float2half(v);
    }
    __syncthreads();
#pragma unroll
    for (int i = 0; i < 16; i++) {
        const int idx = tid + i * 256;
        const int c = idx >> 6, mm = idx & 63;
        g_Xh[(size_t)(b * 64 + c) * N_NODES + m0 + mm] = __float2half(tile[mm][c]);
    }
}

// ---------------------------------------------------------------------------
// Kernel 2b: permute weights_pool [d][k][i][o] -> Wpp[d][o*128 + k*64 + i] f32.
// ---------------------------------------------------------------------------
__global__ __launch_bounds__(256) void k_perm(const float* __restrict__ Wp) {
    const int idx = blockIdx.x * 256 + threadIdx.x;  // < 81920
    const int d = idx >> 13;
    const int r = idx & 8191;        // o*128 + k*64 + i
    const int o = r >> 7;
    const int k = (r >> 6) & 1;
    const int i = r & 63;
    g_Wpp[idx] = Wp[d * 8192 + k * 4096 + i * 64 + o];
}

// ---------------------------------------------------------------------------
// Kernel 2c: Wt[n][p] = sum_d E[n,d] * Wpp[d][p], fp16 out.
// ---------------------------------------------------------------------------
__global__ __launch_bounds__(256) void k_wgen(const float* __restrict__ E) {
    const int p0 = blockIdx.x * 1024;
    const int n0 = blockIdx.y * 32;
    const int tid = threadIdx.x;
    __shared__ float sE[32][EMB];

    for (int s = tid; s < 32 * EMB; s += 256)
        sE[s / EMB][s % EMB] = E[(n0 + s / EMB) * EMB + s % EMB];

    const int p = p0 + tid * 4;
    float4 w[EMB];
#pragma unroll
    for (int d = 0; d < EMB; d++) w[d] = *(const float4*)&g_Wpp[(size_t)d * 8192 + p];
    __syncthreads();

#pragma unroll 4
    for (int nn = 0; nn < 32; nn++) {
        float4 acc = {0.f, 0.f, 0.f, 0.f};
#pragma unroll
        for (int d = 0; d < EMB; d++) {
            const float e = sE[nn][d];
            acc.x = fmaf(e, w[d].x, acc.x);
            acc.y = fmaf(e, w[d].y, acc.y);
            acc.z = fmaf(e, w[d].z, acc.z);
            acc.w = fmaf(e, w[d].w, acc.w);
        }
        uint2 pk;
        pk.x = h2_bits(acc.x, acc.y);
        pk.y = h2_bits(acc.z, acc.w);
        *(uint2*)&g_Wt[(size_t)(n0 + nn) * 8192 + p] = pk;
    }
}

// ---------------------------------------------------------------------------
// Kernel 3: y1 = A @ X via mma.sync fp16; 128x128 tile, KC=64, 3-stage
// cp.async pipeline with ONE __syncthreads per chunk. 2 CTAs/SM.
// ---------------------------------------------------------------------------
#define KC 64
#define ROWB 144
#define TILE_B (128 * ROWB)
#define STAGE_B (2 * TILE_B)          // 36864 B (A + X tiles)
#define SMEM_MMA (3 * STAGE_B)        // 110592 B
#define NT (N_NODES / KC)

__global__ __launch_bounds__(256, 2) void k_mma() {
    extern __shared__ __align__(128) char smem[];
    const uint32_t sb = smem_u32(smem);
    const int tid = threadIdx.x;
    const int wid = tid >> 5;
    const int lane = tid & 31;
    const int wm = wid >> 1;
    const int wn = wid & 1;
    const int n0 = blockIdx.y * 128;
    const int j0 = blockIdx.x * 128;

    int grow[4], gseg[4];
    uint32_t sdst[4];
#pragma unroll
    for (int i = 0; i < 4; i++) {
        const int s = tid + i * 256;
        grow[i] = s >> 3;
        gseg[i] = s & 7;
        sdst[i] = (uint32_t)(grow[i] * ROWB + gseg[i] * 16);
    }

    uint32_t offA[2], offB[4];
#pragma unroll
    for (int mb = 0; mb < 2; mb++)
        offA[mb] = (uint32_t)((wm * 32 + mb * 16 + (lane & 15)) * ROWB + (lane >> 4) * 16);
#pragma unroll
    for (int nb = 0; nb < 4; nb++)
        offB[nb] = (uint32_t)((wn * 64 + nb * 16 + (lane & 15)) * ROWB + (lane >> 4) * 16);

    float acc[2][8][4];
#pragma unroll
    for (int mb = 0; mb < 2; mb++)
#pragma unroll
        for (int nb = 0; nb < 8; nb++)
#pragma unroll
            for (int q = 0; q < 4; q++) acc[mb][nb][q] = 0.f;

    // prologue: chunks 0 and 1 into stages 0 and 1
#pragma unroll
    for (int c = 0; c < 2; c++) {
        const uint32_t st = sb + c * STAGE_B;
        const int m0 = c * KC;
#pragma unroll
        for (int i = 0; i < 4; i++) {
            cp_async16(st + sdst[i],          g_Ah + (size_t)(n0 + grow[i]) * N_NODES + m0 + gseg[i] * 8);
            cp_async16(st + TILE_B + sdst[i], g_Xh + (size_t)(j0 + grow[i]) * N_NODES + m0 + gseg[i] * 8);
        }
        CP_COMMIT();
    }

    int scur = 0, sld = 2;
    for (int t = 0; t < NT; t++) {
        if (t < NT - 1) { CP_WAIT(1); } else { CP_WAIT(0); }
        __syncthreads();

        if (t + 2 < NT) {
            const uint32_t st = sb + sld * STAGE_B;
            const int m0 = (t + 2) * KC;
#pragma unroll
            for (int i = 0; i < 4; i++) {
                cp_async16(st + sdst[i],          g_Ah + (size_t)(n0 + grow[i]) * N_NODES + m0 + gseg[i] * 8);
                cp_async16(st + TILE_B + sdst[i], g_Xh + (size_t)(j0 + grow[i]) * N_NODES + m0 + gseg[i] * 8);
            }
            CP_COMMIT();
        }

        const uint32_t bA = sb + scur * STAGE_B;
        const uint32_t bB = bA + TILE_B;
#pragma unroll
        for (int ks = 0; ks < 4; ks++) {
            const uint32_t ko = ks * 32;
            uint32_t ah[2][4];
#pragma unroll
            for (int mb = 0; mb < 2; mb++) ldsm4(ah[mb], bA + offA[mb] + ko);
#pragma unroll
            for (int nb = 0; nb < 4; nb++) {
                uint32_t bh[4];
                ldsm4(bh, bB + offB[nb] + ko);
#pragma unroll
                for (int mb = 0; mb < 2; mb++) {
                    mma_f16(acc[mb][nb * 2 + 0], ah[mb], bh[0], bh[2]);
                    mma_f16(acc[mb][nb * 2 + 1], ah[mb], bh[1], bh[3]);
                }
            }
        }
        scur = (scur == 2) ? 0 : scur + 1;
        sld = (sld == 2) ? 0 : sld + 1;
    }

    const int b = (j0 + wn * 64) >> 6;
#pragma unroll
    for (int mb = 0; mb < 2; mb++) {
        const int nrow = n0 + wm * 32 + mb * 16 + (lane >> 2);
#pragma unroll
        for (int nb = 0; nb < 8; nb++) {
            const int c = nb * 8 + (lane & 3) * 2;
            const uint32_t v0 = h2_bits(acc[mb][nb][0], acc[mb][nb][1]);
            const uint32_t v1 = h2_bits(acc[mb][nb][2], acc[mb][nb][3]);
            *(uint32_t*)&g_y1h[((size_t)b * N_NODES + nrow) * CI + c] = v0;
            *(uint32_t*)&g_y1h[((size_t)b * N_NODES + nrow + 8) * CI + c] = v1;
        }
    }
}

// ---------------------------------------------------------------------------
// Kernel 4: out[b,o] = A[b,ki] * Wt[o,ki] + bias, per node, tensor cores.
// ---------------------------------------------------------------------------
#define KO_PITCH 272                   // bytes per smem row (136 halfs)

__global__ __launch_bounds__(128) void k_out(const float* __restrict__ E,
                                             const float* __restrict__ bp,
                                             float* __restrict__ out) {
    __shared__ __align__(16) char sAraw[64 * KO_PITCH];
    __shared__ __align__(16) char sWraw[64 * KO_PITCH];
    __shared__ float sbias[64];
    __shared__ float sE[EMB];

    const int n = blockIdx.x;
    const int tid = threadIdx.x;
    const int wid = tid >> 5;
    const int lane = tid & 31;
    const uint32_t aA = smem_u32(sAraw);
    const uint32_t aW = smem_u32(sWraw);

    // W tile: 64 rows x 256B = 1024 x 16B segments
#pragma unroll
    for (int i = 0; i < 8; i++) {
        const int s = tid + i * 128;          // 0..1023
        const int row = s >> 4, seg = s & 15;
        cp_async16(aW + row * KO_PITCH + seg * 16,
                   g_Wt + (size_t)n * 8192 + row * 128 + seg * 8);
    }
    // A tile: 64 rows; x fills bytes [0,128), y1 fills [128,256)
#pragma unroll
    for (int i = 0; i < 4; i++) {
        const int s = tid + i * 128;          // 0..511
        const int b = s >> 3, seg = s & 7;
        cp_async16(aA + b * KO_PITCH + seg * 16,
                   g_xh16 + ((size_t)b * N_NODES + n) * CI + seg * 8);
        cp_async16(aA + b * KO_PITCH + 128 + seg * 16,
                   g_y1h + ((size_t)b * N_NODES + n) * CI + seg * 8);
    }
    CP_COMMIT();

    if (tid < EMB) sE[tid] = E[n * EMB + tid];
    __syncthreads();
    if (tid < 64) {
        float acc = 0.f;
#pragma unroll
        for (int d = 0; d < EMB; d++) acc = fmaf(sE[d], bp[d * 64 + tid], acc);
        sbias[tid] = acc;
    }
    CP_WAIT(0);
    __syncthreads();

    const uint32_t offA = (uint32_t)((wid * 16 + (lane & 15)) * KO_PITCH + (lane >> 4) * 16);
    uint32_t offB[4];
#pragma unroll
    for (int nb = 0; nb < 4; nb++)
        offB[nb] = (uint32_t)((nb * 16 + (lane & 15)) * KO_PITCH + (lane >> 4) * 16);

    float acc[8][4];
#pragma unroll
    for (int nb = 0; nb < 8; nb++)
#pragma unroll
        for (int q = 0; q < 4; q++) acc[nb][q] = 0.f;

#pragma unroll
    for (int ks = 0; ks < 8; ks++) {
        const uint32_t ko = ks * 32;
        uint32_t ah[4];
        ldsm4(ah, aA + offA + ko);
#pragma unroll
        for (int nb = 0; nb < 4; nb++) {
            uint32_t bh[4];
            ldsm4(bh, aW + offB[nb] + ko);
            mma_f16(acc[nb * 2 + 0], ah, bh[0], bh[2]);
            mma_f16(acc[nb * 2 + 1], ah, bh[1], bh[3]);
        }
    }

    const int brow = wid * 16 + (lane >> 2);
#pragma unroll
    for (int nb = 0; nb < 8; nb++) {
        const int o = nb * 8 + (lane & 3) * 2;
        const float2 bias = *(const float2*)&sbias[o];
        float2 v0 = {acc[nb][0] + bias.x, acc[nb][1] + bias.y};
        float2 v1 = {acc[nb][2] + bias.x, acc[nb][3] + bias.y};
        *(float2*)&out[((size_t)brow * N_NODES + n) * CO + o] = v0;
        *(float2*)&out[((size_t)(brow + 8) * N_NODES + n) * CO + o] = v1;
    }
}

// ---------------------------------------------------------------------------
extern "C" void kernel_launch(void* const* d_in, const int* in_sizes, int n_in,
                              void* d_out, int out_size) {
    const float* x  = (const float*)d_in[0];
    const float* E  = (const float*)d_in[1];
    const float* Wp = (const float*)d_in[2];
    const float* bp = (const float*)d_in[3];
    float* out = (float*)d_out;

    cudaFuncSetAttribute(k_mma, cudaFuncAttributeMaxDynamicSharedMemorySize, SMEM_MMA);

    k_softmax<<<N_NODES / SM_ROWS, 256>>>(E);
    dim3 gT(N_NODES / 64, NBATCH);
    k_transpose<<<gT, 256>>>(x);
    k_perm<<<(EMB * 8192) / 256, 256>>>(Wp);
    dim3 gW(8192 / 1024, N_NODES / 32);
    k_wgen<<<gW, 256>>>(E);
    dim3 gM(N_NODES / 128, N_NODES / 128);
    k_mma<<<gM, 256, SMEM_MMA>>>();
    k_out<<<N_NODES, 128>>>(E, bp, out);
}

// round 14
// speedup vs baseline: 1.4560x; 1.0366x over previous
#include <cuda_runtime.h>
#include <cuda_fp16.h>
#include <cstdint>

#define N_NODES 4096
#define EMB 10
#define NBATCH 64
#define CI 64
#define CO 64

// ---------------- device scratch (allocation-free rule) --------------------
__device__ __half g_Ah[(size_t)N_NODES * N_NODES];    // softmax(relu(EE^T)) fp16
__device__ __half g_Xh[(size_t)N_NODES * N_NODES];    // X^T[j=b*64+c][m] fp16
__device__ __half g_xh16[(size_t)NBATCH * N_NODES * CI]; // x fp16 [b][n][i]
__device__ __half g_y1h[(size_t)NBATCH * N_NODES * CI];  // y1 fp16 [b][n][c]
__device__ float  g_Wpp[(size_t)EMB * 8192];          // permuted pool [d][o*128+k*64+i]
__device__ __half g_Wt[(size_t)N_NODES * 8192];       // per-node W^T fp16 [n][o][ki]

// ---------------- PTX helpers ---------------------------------------------
__device__ __forceinline__ uint32_t smem_u32(const void* p) {
    uint32_t a;
    asm("{ .reg .u64 t; cvta.to.shared.u64 t, %1; cvt.u32.u64 %0, t; }" : "=r"(a) : "l"(p));
    return a;
}
__device__ __forceinline__ void cp_async16(uint32_t dst, const void* src) {
    asm volatile("cp.async.cg.shared.global [%0], [%1], 16;" :: "r"(dst), "l"(src));
}
#define CP_COMMIT()  asm volatile("cp.async.commit_group;" ::: "memory")
#define CP_WAIT(N)   asm volatile("cp.async.wait_group %0;" :: "n"(N) : "memory")

__device__ __forceinline__ void ldsm4(uint32_t* r, uint32_t addr) {
    asm volatile("ldmatrix.sync.aligned.m8n8.x4.shared.b16 {%0,%1,%2,%3}, [%4];"
        : "=r"(r[0]), "=r"(r[1]), "=r"(r[2]), "=r"(r[3]) : "r"(addr));
}
__device__ __forceinline__ void mma_f16(float* c, const uint32_t* a,
                                        uint32_t b0, uint32_t b1) {
    asm volatile("mma.sync.aligned.m16n8k16.row.col.f32.f16.f16.f32 "
        "{%0,%1,%2,%3}, {%4,%5,%6,%7}, {%8,%9}, {%0,%1,%2,%3};"
        : "+f"(c[0]), "+f"(c[1]), "+f"(c[2]), "+f"(c[3])
        : "r"(a[0]), "r"(a[1]), "r"(a[2]), "r"(a[3]), "r"(b0), "r"(b1));
}
__device__ __forceinline__ uint32_t h2_bits(float lo, float hi) {
    __half2 h = __floats2half2_rn(lo, hi);
    uint32_t u;
    memcpy(&u, &h, 4);
    return u;
}

// ---------------------------------------------------------------------------
// Kernel A (k_prep): fused transpose / softmax / perm, dispatched on blockIdx.
//   [0, 4096)     : transpose x -> X^T fp16 + x fp16
//   [4096, 5120)  : softmax(relu(E E^T)) rows (4 rows per CTA)
//   [5120, 5440)  : permute weights_pool -> g_Wpp
// ---------------------------------------------------------------------------
#define SM_ROWS 4
#define PREP_TRANS 4096
#define PREP_SMAX  (PREP_TRANS + N_NODES / SM_ROWS)     // +1024 = 5120
#define PREP_PERM  (PREP_SMAX + (EMB * 8192) / 256)     // +320  = 5440

__global__ __launch_bounds__(256) void k_prep(const float* __restrict__ x,
                                              const float* __restrict__ E,
                                              const float* __restrict__ Wp) {
    __shared__ __align__(16) char sbuf[64 * 65 * 4];
    const int bidx = blockIdx.x;
    const int tid = threadIdx.x;

    if (bidx < PREP_TRANS) {
        // ---- transpose: b = bidx>>6, m0 = (bidx&63)*64 ----
        float (*tile)[65] = (float(*)[65])sbuf;
        const int b = bidx >> 6;
        const int m0 = (bidx & 63) * 64;
#pragma unroll
        for (int i = 0; i < 16; i++) {
            const int idx = tid + i * 256;
            const int mi = idx >> 6, c = idx & 63;
            const float v = x[((size_t)b * N_NODES + m0 + mi) * CI + c];
            tile[mi][c] = v;
            g_xh16[((size_t)b * N_NODES + m0 + mi) * CI + c] = __float2half(v);
        }
        __syncthreads();
#pragma unroll
        for (int i = 0; i < 16; i++) {
            const int idx = tid + i * 256;
            const int c = idx >> 6, mm = idx & 63;
            g_Xh[(size_t)(b * 64 + c) * N_NODES + m0 + mm] = __float2half(tile[mm][c]);
        }
    } else if (bidx < PREP_SMAX) {
        // ---- softmax: 4 rows per CTA, two passes, no max-subtraction ----
        float* sER = (float*)sbuf;                         // [SM_ROWS*EMB]
        float* sred = sER + SM_ROWS * EMB;                 // [8][SM_ROWS]
        float* sinv = sred + 8 * SM_ROWS;                  // [SM_ROWS]
        const int r0 = (bidx - PREP_TRANS) * SM_ROWS;

        if (tid < SM_ROWS * EMB) sER[tid] = E[r0 * EMB + tid];
        __syncthreads();

        float er[SM_ROWS][EMB];
#pragma unroll
        for (int r = 0; r < SM_ROWS; r++)
#pragma unroll
            for (int d = 0; d < EMB; d++) er[r][d] = sER[r * EMB + d];

        float ssum[SM_ROWS];
#pragma unroll
        for (int r = 0; r < SM_ROWS; r++) ssum[r] = 0.f;

        for (int it = 0; it < 16; it++) {
            const int m = tid + it * 256;
            float em[EMB];
#pragma unroll
            for (int d = 0; d < EMB; d++) em[d] = __ldg(E + m * EMB + d);
#pragma unroll
            for (int r = 0; r < SM_ROWS; r++) {
                float dot = 0.f;
#pragma unroll
                for (int d = 0; d < EMB; d++) dot = fmaf(em[d], er[r][d], dot);
                ssum[r] += __expf(fmaxf(dot, 0.f));
            }
        }
#pragma unroll
        for (int r = 0; r < SM_ROWS; r++)
#pragma unroll
            for (int o = 16; o; o >>= 1) ssum[r] += __shfl_xor_sync(0xffffffffu, ssum[r], o);
        if ((tid & 31) == 0) {
#pragma unroll
            for (int r = 0; r < SM_ROWS; r++) sred[(tid >> 5) * SM_ROWS + r] = ssum[r];
        }
        __syncthreads();
        if (tid < SM_ROWS) {
            float s = 0.f;
#pragma unroll
            for (int w = 0; w < 8; w++) s += sred[w * SM_ROWS + tid];
            sinv[tid] = 1.0f / s;
        }
        __syncthreads();
        float inv[SM_ROWS];
#pragma unroll
        for (int r = 0; r < SM_ROWS; r++) inv[r] = sinv[r];

        for (int it = 0; it < 16; it++) {
            const int m = tid + it * 256;
            float em[EMB];
#pragma unroll
            for (int d = 0; d < EMB; d++) em[d] = __ldg(E + m * EMB + d);
#pragma unroll
            for (int r = 0; r < SM_ROWS; r++) {
                float dot = 0.f;
#pragma unroll
                for (int d = 0; d < EMB; d++) dot = fmaf(em[d], er[r][d], dot);
                g_Ah[(size_t)(r0 + r) * N_NODES + m] =
                    __float2half(__expf(fmaxf(dot, 0.f)) * inv[r]);
            }
        }
    } else {
        // ---- perm: weights_pool [d][k][i][o] -> Wpp[d][o*128+k*64+i] ----
        const int idx = (bidx - PREP_SMAX) * 256 + tid;    // < 81920
        const int d = idx >> 13;
        const int r = idx & 8191;
        const int o = r >> 7;
        const int k = (r >> 6) & 1;
        const int i = r & 63;
        g_Wpp[idx] = Wp[d * 8192 + k * 4096 + i * 64 + o];
    }
}

// ---------------------------------------------------------------------------
// Kernel B (k_main): fused diffusion GEMM + Wt generation.
//   [0, 1024)    : y1 = A @ X  (mma.sync fp16, 128x128 tile, KC=64, 3-stage)
//   [1024, 2048) : Wt[n][p] = sum_d E[n,d] * Wpp[d][p]  (backfills mma tail)
// ---------------------------------------------------------------------------
#define KC 64
#define ROWB 144
#define TILE_B (128 * ROWB)
#define STAGE_B (2 * TILE_B)
#define SMEM_MMA (3 * STAGE_B)        // 110592 B
#define NT (N_NODES / KC)

__global__ __launch_bounds__(256, 2) void k_main(const float* __restrict__ E) {
    extern __shared__ __align__(128) char smem[];
    const int tid = threadIdx.x;

    if (blockIdx.x >= 1024) {
        // ---- wgen ----
        const int wb = blockIdx.x - 1024;
        const int p0 = (wb & 7) * 1024;
        const int n0 = (wb >> 3) * 32;
        __shared__ float sE[32][EMB];

        for (int s = tid; s < 32 * EMB; s += 256)
            sE[s / EMB][s % EMB] = E[(n0 + s / EMB) * EMB + s % EMB];

        const int p = p0 + tid * 4;
        float4 w[EMB];
#pragma unroll
        for (int d = 0; d < EMB; d++) w[d] = *(const float4*)&g_Wpp[(size_t)d * 8192 + p];
        __syncthreads();

#pragma unroll 4
        for (int nn = 0; nn < 32; nn++) {
            float4 acc = {0.f, 0.f, 0.f, 0.f};
#pragma unroll
            for (int d = 0; d < EMB; d++) {
                const float e = sE[nn][d];
                acc.x = fmaf(e, w[d].x, acc.x);
                acc.y = fmaf(e, w[d].y, acc.y);
                acc.z = fmaf(e, w[d].z, acc.z);
                acc.w = fmaf(e, w[d].w, acc.w);
            }
            uint2 pk;
            pk.x = h2_bits(acc.x, acc.y);
            pk.y = h2_bits(acc.z, acc.w);
            *(uint2*)&g_Wt[(size_t)(n0 + nn) * 8192 + p] = pk;
        }
        return;
    }

    // ---- mma tile ----
    const uint32_t sb = smem_u32(smem);
    const int wid = tid >> 5;
    const int lane = tid & 31;
    const int wm = wid >> 1;
    const int wn = wid & 1;
    const int n0 = (blockIdx.x >> 5) * 128;
    const int j0 = (blockIdx.x & 31) * 128;

    int grow[4], gseg[4];
    uint32_t sdst[4];
#pragma unroll
    for (int i = 0; i < 4; i++) {
        const int s = tid + i * 256;
        grow[i] = s >> 3;
        gseg[i] = s & 7;
        sdst[i] = (uint32_t)(grow[i] * ROWB + gseg[i] * 16);
    }

    uint32_t offA[2], offB[4];
#pragma unroll
    for (int mb = 0; mb < 2; mb++)
        offA[mb] = (uint32_t)((wm * 32 + mb * 16 + (lane & 15)) * ROWB + (lane >> 4) * 16);
#pragma unroll
    for (int nb = 0; nb < 4; nb++)
        offB[nb] = (uint32_t)((wn * 64 + nb * 16 + (lane & 15)) * ROWB + (lane >> 4) * 16);

    float acc[2][8][4];
#pragma unroll
    for (int mb = 0; mb < 2; mb++)
#pragma unroll
        for (int nb = 0; nb < 8; nb++)
#pragma unroll
            for (int q = 0; q < 4; q++) acc[mb][nb][q] = 0.f;

    // prologue: chunks 0 and 1 into stages 0 and 1
#pragma unroll
    for (int c = 0; c < 2; c++) {
        const uint32_t st = sb + c * STAGE_B;
        const int m0 = c * KC;
#pragma unroll
        for (int i = 0; i < 4; i++) {
            cp_async16(st + sdst[i],          g_Ah + (size_t)(n0 + grow[i]) * N_NODES + m0 + gseg[i] * 8);
            cp_async16(st + TILE_B + sdst[i], g_Xh + (size_t)(j0 + grow[i]) * N_NODES + m0 + gseg[i] * 8);
        }
        CP_COMMIT();
    }

    int scur = 0, sld = 2;
    for (int t = 0; t < NT; t++) {
        if (t < NT - 1) { CP_WAIT(1); } else { CP_WAIT(0); }
        __syncthreads();

        if (t + 2 < NT) {
            const uint32_t st = sb + sld * STAGE_B;
            const int m0 = (t + 2) * KC;
#pragma unroll
            for (int i = 0; i < 4; i++) {
                cp_async16(st + sdst[i],          g_Ah + (size_t)(n0 + grow[i]) * N_NODES + m0 + gseg[i] * 8);
                cp_async16(st + TILE_B + sdst[i], g_Xh + (size_t)(j0 + grow[i]) * N_NODES + m0 + gseg[i] * 8);
            }
            CP_COMMIT();
        }

        const uint32_t bA = sb + scur * STAGE_B;
        const uint32_t bB = bA + TILE_B;
#pragma unroll
        for (int ks = 0; ks < 4; ks++) {
            const uint32_t ko = ks * 32;
            uint32_t ah[2][4];
#pragma unroll
            for (int mb = 0; mb < 2; mb++) ldsm4(ah[mb], bA + offA[mb] + ko);
#pragma unroll
            for (int nb = 0; nb < 4; nb++) {
                uint32_t bh[4];
                ldsm4(bh, bB + offB[nb] + ko);
#pragma unroll
                for (int mb = 0; mb < 2; mb++) {
                    mma_f16(acc[mb][nb * 2 + 0], ah[mb], bh[0], bh[2]);
                    mma_f16(acc[mb][nb * 2 + 1], ah[mb], bh[1], bh[3]);
                }
            }
        }
        scur = (scur == 2) ? 0 : scur + 1;
        sld = (sld == 2) ? 0 : sld + 1;
    }

    const int b = (j0 + wn * 64) >> 6;
#pragma unroll
    for (int mb = 0; mb < 2; mb++) {
        const int nrow = n0 + wm * 32 + mb * 16 + (lane >> 2);
#pragma unroll
        for (int nb = 0; nb < 8; nb++) {
            const int c = nb * 8 + (lane & 3) * 2;
            const uint32_t v0 = h2_bits(acc[mb][nb][0], acc[mb][nb][1]);
            const uint32_t v1 = h2_bits(acc[mb][nb][2], acc[mb][nb][3]);
            *(uint32_t*)&g_y1h[((size_t)b * N_NODES + nrow) * CI + c] = v0;
            *(uint32_t*)&g_y1h[((size_t)b * N_NODES + nrow + 8) * CI + c] = v1;
        }
    }
}

// ---------------------------------------------------------------------------
// Kernel C (k_out): out[b,o] = A[b,ki] * Wt[o,ki] + bias, per node, HMMA.
// ---------------------------------------------------------------------------
#define KO_PITCH 272                   // bytes per smem row (136 halfs)

__global__ __launch_bounds__(128) void k_out(const float* __restrict__ E,
                                             const float* __restrict__ bp,
                                             float* __restrict__ out) {
    __shared__ __align__(16) char sAraw[64 * KO_PITCH];
    __shared__ __align__(16) char sWraw[64 * KO_PITCH];
    __shared__ float sbias[64];
    __shared__ float sE[EMB];

    const int n = blockIdx.x;
    const int tid = threadIdx.x;
    const int wid = tid >> 5;
    const int lane = tid & 31;
    const uint32_t aA = smem_u32(sAraw);
    const uint32_t aW = smem_u32(sWraw);

    // W tile: 64 rows x 256B = 1024 x 16B segments
#pragma unroll
    for (int i = 0; i < 8; i++) {
        const int s = tid + i * 128;          // 0..1023
        const int row = s >> 4, seg = s & 15;
        cp_async16(aW + row * KO_PITCH + seg * 16,
                   g_Wt + (size_t)n * 8192 + row * 128 + seg * 8);
    }
    // A tile: 64 rows; x fills bytes [0,128), y1 fills [128,256)
#pragma unroll
    for (int i = 0; i < 4; i++) {
        const int s = tid + i * 128;          // 0..511
        const int b = s >> 3, seg = s & 7;
        cp_async16(aA + b * KO_PITCH + seg * 16,
                   g_xh16 + ((size_t)b * N_NODES + n) * CI + seg * 8);
        cp_async16(aA + b * KO_PITCH + 128 + seg * 16,
                   g_y1h + ((size_t)b * N_NODES + n) * CI + seg * 8);
    }
    CP_COMMIT();

    if (tid < EMB) sE[tid] = E[n * EMB + tid];
    __syncthreads();
    if (tid < 64) {
        float acc = 0.f;
#pragma unroll
        for (int d = 0; d < EMB; d++) acc = fmaf(sE[d], bp[d * 64 + tid], acc);
        sbias[tid] = acc;
    }
    CP_WAIT(0);
    __syncthreads();

    const uint32_t offA = (uint32_t)((wid * 16 + (lane & 15)) * KO_PITCH + (lane >> 4) * 16);
    uint32_t offB[4];
#pragma unroll
    for (int nb = 0; nb < 4; nb++)
        offB[nb] = (uint32_t)((nb * 16 + (lane & 15)) * KO_PITCH + (lane >> 4) * 16);

    float acc[8][4];
#pragma unroll
    for (int nb = 0; nb < 8; nb++)
#pragma unroll
        for (int q = 0; q < 4; q++) acc[nb][q] = 0.f;

#pragma unroll
    for (int ks = 0; ks < 8; ks++) {
        const uint32_t ko = ks * 32;
        uint32_t ah[4];
        ldsm4(ah, aA + offA + ko);
#pragma unroll
        for (int nb = 0; nb < 4; nb++) {
            uint32_t bh[4];
            ldsm4(bh, aW + offB[nb] + ko);
            mma_f16(acc[nb * 2 + 0], ah, bh[0], bh[2]);
            mma_f16(acc[nb * 2 + 1], ah, bh[1], bh[3]);
        }
    }

    const int brow = wid * 16 + (lane >> 2);
#pragma unroll
    for (int nb = 0; nb < 8; nb++) {
        const int o = nb * 8 + (lane & 3) * 2;
        const float2 bias = *(const float2*)&sbias[o];
        float2 v0 = {acc[nb][0] + bias.x, acc[nb][1] + bias.y};
        float2 v1 = {acc[nb][2] + bias.x, acc[nb][3] + bias.y};
        *(float2*)&out[((size_t)brow * N_NODES + n) * CO + o] = v0;
        *(float2*)&out[((size_t)(brow + 8) * N_NODES + n) * CO + o] = v1;
    }
}

// ---------------------------------------------------------------------------
extern "C" void kernel_launch(void* const* d_in, const int* in_sizes, int n_in,
                              void* d_out, int out_size) {
    const float* x  = (const float*)d_in[0];
    const float* E  = (const float*)d_in[1];
    const float* Wp = (const float*)d_in[2];
    const float* bp = (const float*)d_in[3];
    float* out = (float*)d_out;

    cudaFuncSetAttribute(k_main, cudaFuncAttributeMaxDynamicSharedMemorySize, SMEM_MMA);

    k_prep<<<PREP_PERM, 256>>>(x, E, Wp);
    k_main<<<2048, 256, SMEM_MMA>>>(E);
    k_out<<<N_NODES, 128>>>(E, bp, out);
}

// round 15
// speedup vs baseline: 1.4840x; 1.0193x over previous
#include <cuda_runtime.h>
#include <cuda_fp16.h>
#include <cstdint>

#define N_NODES 4096
#define EMB 10
#define NBATCH 64
#define CI 64
#define CO 64

// ---------------- device scratch (allocation-free rule) --------------------
__device__ __half g_Ah[(size_t)N_NODES * N_NODES];    // softmax(relu(EE^T)) fp16
__device__ __half g_Xh[(size_t)N_NODES * N_NODES];    // X^T[j=b*64+c][m] fp16
__device__ __half g_xh16[(size_t)NBATCH * N_NODES * CI]; // x fp16 [b][n][i]
__device__ __half g_y1h[(size_t)NBATCH * N_NODES * CI];  // y1 fp16 [b][n][c]
__device__ float  g_Wpp[(size_t)EMB * 8192];          // permuted pool [d][o*128+k*64+i]
__device__ __half g_Wt[(size_t)N_NODES * 8192];       // per-node W^T fp16 [n][o][ki]
__device__ int    g_rowdone[32];                      // mma row-block completion (32 j-tiles each)
__device__ int    g_wdone[128];                       // Wt 32-node-group completion (8 p-blocks each)

// ---------------- PTX helpers ---------------------------------------------
__device__ __forceinline__ uint32_t smem_u32(const void* p) {
    uint32_t a;
    asm("{ .reg .u64 t; cvta.to.shared.u64 t, %1; cvt.u32.u64 %0, t; }" : "=r"(a) : "l"(p));
    return a;
}
__device__ __forceinline__ void cp_async16(uint32_t dst, const void* src) {
    asm volatile("cp.async.cg.shared.global [%0], [%1], 16;" :: "r"(dst), "l"(src));
}
#define CP_COMMIT()  asm volatile("cp.async.commit_group;" ::: "memory")
#define CP_WAIT(N)   asm volatile("cp.async.wait_group %0;" :: "n"(N) : "memory")

__device__ __forceinline__ void ldsm4(uint32_t* r, uint32_t addr) {
    asm volatile("ldmatrix.sync.aligned.m8n8.x4.shared.b16 {%0,%1,%2,%3}, [%4];"
        : "=r"(r[0]), "=r"(r[1]), "=r"(r[2]), "=r"(r[3]) : "r"(addr));
}
__device__ __forceinline__ void mma_f16(float* c, const uint32_t* a,
                                        uint32_t b0, uint32_t b1) {
    asm volatile("mma.sync.aligned.m16n8k16.row.col.f32.f16.f16.f32 "
        "{%0,%1,%2,%3}, {%4,%5,%6,%7}, {%8,%9}, {%0,%1,%2,%3};"
        : "+f"(c[0]), "+f"(c[1]), "+f"(c[2]), "+f"(c[3])
        : "r"(a[0]), "r"(a[1]), "r"(a[2]), "r"(a[3]), "r"(b0), "r"(b1));
}
__device__ __forceinline__ uint32_t h2_bits(float lo, float hi) {
    __half2 h = __floats2half2_rn(lo, hi);
    uint32_t u;
    memcpy(&u, &h, 4);
    return u;
}

// ---------------------------------------------------------------------------
// Kernel A (k_prep): fused transpose / softmax / perm / counter-zero.
//   [0, 4096)     : transpose x -> X^T fp16 + x fp16 (vectorized half2 stores)
//   [4096, 5120)  : softmax(relu(E E^T)) rows (4 rows per CTA)
//   [5120, 5440)  : permute weights_pool -> g_Wpp
//   [5440]        : zero completion counters (graph-replay-safe)
// ---------------------------------------------------------------------------
#define SM_ROWS 4
#define PREP_TRANS 4096
#define PREP_SMAX  (PREP_TRANS + N_NODES / SM_ROWS)     // 5120
#define PREP_PERM  (PREP_SMAX + (EMB * 8192) / 256)     // 5440
#define PREP_GRID  (PREP_PERM + 1)

__global__ __launch_bounds__(256) void k_prep(const float* __restrict__ x,
                                              const float* __restrict__ E,
                                              const float* __restrict__ Wp) {
    __shared__ __align__(16) char sbuf[64 * 65 * 4];
    const int bidx = blockIdx.x;
    const int tid = threadIdx.x;

    if (bidx < PREP_TRANS) {
        // ---- transpose: b = bidx>>6, m0 = (bidx&63)*64 ----
        float (*tile)[65] = (float(*)[65])sbuf;
        const int b = bidx >> 6;
        const int m0 = (bidx & 63) * 64;
#pragma unroll
        for (int i = 0; i < 8; i++) {
            const int idx = tid + i * 256;      // 0..2047
            const int mi = idx >> 5;            // 0..63
            const int cp = (idx & 31) * 2;      // even c
            const float2 v = *(const float2*)&x[((size_t)b * N_NODES + m0 + mi) * CI + cp];
            tile[mi][cp] = v.x;
            tile[mi][cp + 1] = v.y;
            *(uint32_t*)&g_xh16[((size_t)b * N_NODES + m0 + mi) * CI + cp] = h2_bits(v.x, v.y);
        }
        __syncthreads();
#pragma unroll
        for (int i = 0; i < 8; i++) {
            const int idx = tid + i * 256;
            const int c = idx >> 5;             // 0..63
            const int pm = (idx & 31) * 2;      // even m
            *(uint32_t*)&g_Xh[(size_t)(b * 64 + c) * N_NODES + m0 + pm] =
                h2_bits(tile[pm][c], tile[pm + 1][c]);
        }
    } else if (bidx < PREP_SMAX) {
        // ---- softmax: 4 rows per CTA, two passes, no max-subtraction ----
        float* sER = (float*)sbuf;
        float* sred = sER + SM_ROWS * EMB;
        float* sinv = sred + 8 * SM_ROWS;
        const int r0 = (bidx - PREP_TRANS) * SM_ROWS;

        if (tid < SM_ROWS * EMB) sER[tid] = E[r0 * EMB + tid];
        __syncthreads();

        float er[SM_ROWS][EMB];
#pragma unroll
        for (int r = 0; r < SM_ROWS; r++)
#pragma unroll
            for (int d = 0; d < EMB; d++) er[r][d] = sER[r * EMB + d];

        float ssum[SM_ROWS];
#pragma unroll
        for (int r = 0; r < SM_ROWS; r++) ssum[r] = 0.f;

        for (int it = 0; it < 16; it++) {
            const int m = tid + it * 256;
            float em[EMB];
#pragma unroll
            for (int d = 0; d < EMB; d++) em[d] = __ldg(E + m * EMB + d);
#pragma unroll
            for (int r = 0; r < SM_ROWS; r++) {
                float dot = 0.f;
#pragma unroll
                for (int d = 0; d < EMB; d++) dot = fmaf(em[d], er[r][d], dot);
                ssum[r] += __expf(fmaxf(dot, 0.f));
            }
        }
#pragma unroll
        for (int r = 0; r < SM_ROWS; r++)
#pragma unroll
            for (int o = 16; o; o >>= 1) ssum[r] += __shfl_xor_sync(0xffffffffu, ssum[r], o);
        if ((tid & 31) == 0) {
#pragma unroll
            for (int r = 0; r < SM_ROWS; r++) sred[(tid >> 5) * SM_ROWS + r] = ssum[r];
        }
        __syncthreads();
        if (tid < SM_ROWS) {
            float s = 0.f;
#pragma unroll
            for (int w = 0; w < 8; w++) s += sred[w * SM_ROWS + tid];
            sinv[tid] = 1.0f / s;
        }
        __syncthreads();
        float inv[SM_ROWS];
#pragma unroll
        for (int r = 0; r < SM_ROWS; r++) inv[r] = sinv[r];

        for (int it = 0; it < 16; it++) {
            const int m = tid + it * 256;
            float em[EMB];
#pragma unroll
            for (int d = 0; d < EMB; d++) em[d] = __ldg(E + m * EMB + d);
#pragma unroll
            for (int r = 0; r < SM_ROWS; r++) {
                float dot = 0.f;
#pragma unroll
                for (int d = 0; d < EMB; d++) dot = fmaf(em[d], er[r][d], dot);
                g_Ah[(size_t)(r0 + r) * N_NODES + m] =
                    __float2half(__expf(fmaxf(dot, 0.f)) * inv[r]);
            }
        }
    } else if (bidx < PREP_PERM) {
        // ---- perm ----
        const int idx = (bidx - PREP_SMAX) * 256 + tid;
        const int d = idx >> 13;
        const int r = idx & 8191;
        const int o = r >> 7;
        const int k = (r >> 6) & 1;
        const int i = r & 63;
        g_Wpp[idx] = Wp[d * 8192 + k * 4096 + i * 64 + o];
    } else {
        // ---- zero counters ----
        if (tid < 32) g_rowdone[tid] = 0;
        else if (tid < 160) g_wdone[tid - 32] = 0;
    }
}

// ---------------------------------------------------------------------------
// Kernel B (k_main): fused diffusion GEMM + Wt generation + output GEMM.
//   [0, 1024)    : y1 = A @ X  (mma.sync fp16; increments g_rowdone)
//   [1024, 2048) : Wt gen      (increments g_wdone)
//   [2048, 4096) : out GEMM, 2 nodes/CTA (spins on counters, then HMMA)
// ---------------------------------------------------------------------------
#define KC 64
#define ROWB 144
#define TILE_B (128 * ROWB)
#define STAGE_B (2 * TILE_B)
#define SMEM_MMA (3 * STAGE_B)        // 110592 B
#define NT (N_NODES / KC)
#define KO_PITCH 272                   // out-tile smem row pitch
#define KO_TILE (64 * KO_PITCH)        // 17408 B
#define KO_NODE (2 * KO_TILE)          // A + W per node = 34816 B

__global__ __launch_bounds__(256, 2) void k_main(const float* __restrict__ E,
                                                 const float* __restrict__ bp,
                                                 float* __restrict__ out) {
    extern __shared__ __align__(128) char smem[];
    const int tid = threadIdx.x;

    if (blockIdx.x >= 2048) {
        // =================== out GEMM (consumer) ===================
        const int ci = blockIdx.x - 2048;
        const int nbase = ci * 2;
        const int h = tid >> 7;        // node half
        const int tl = tid & 127;
        const int n = nbase + h;
        const int wid4 = tl >> 5;
        const int lane = tl & 31;

        // wait for producers
        if (tid == 0) {
            volatile int* rd = g_rowdone;
            volatile int* wd = g_wdone;
            while (rd[nbase >> 7] < 32) __nanosleep(200);
            while (wd[nbase >> 5] < 8) __nanosleep(200);
        }
        __syncthreads();
        __threadfence();

        char* sA = smem + h * KO_NODE;
        char* sW = smem + h * KO_NODE + KO_TILE;
        float* sbias = (float*)(smem + 2 * KO_NODE) + h * 64;
        float* sE = (float*)(smem + 2 * KO_NODE + 512) + h * 16;
        const uint32_t aA = smem_u32(sA);
        const uint32_t aW = smem_u32(sW);

        // W tile: 64 rows x 256B = 1024 x 16B segments
#pragma unroll
        for (int i = 0; i < 8; i++) {
            const int s = tl + i * 128;
            const int row = s >> 4, seg = s & 15;
            cp_async16(aW + row * KO_PITCH + seg * 16,
                       g_Wt + (size_t)n * 8192 + row * 128 + seg * 8);
        }
        // A tile: x in [0,128), y1 in [128,256) per row
#pragma unroll
        for (int i = 0; i < 4; i++) {
            const int s = tl + i * 128;
            const int b = s >> 3, seg = s & 7;
            cp_async16(aA + b * KO_PITCH + seg * 16,
                       g_xh16 + ((size_t)b * N_NODES + n) * CI + seg * 8);
            cp_async16(aA + b * KO_PITCH + 128 + seg * 16,
                       g_y1h + ((size_t)b * N_NODES + n) * CI + seg * 8);
        }
        CP_COMMIT();

        if (tl < EMB) sE[tl] = E[n * EMB + tl];
        __syncthreads();
        if (tl < 64) {
            float acc = 0.f;
#pragma unroll
            for (int d = 0; d < EMB; d++) acc = fmaf(sE[d], bp[d * 64 + tl], acc);
            sbias[tl] = acc;
        }
        CP_WAIT(0);
        __syncthreads();

        const uint32_t offA = (uint32_t)((wid4 * 16 + (lane & 15)) * KO_PITCH + (lane >> 4) * 16);
        uint32_t offB[4];
#pragma unroll
        for (int nb = 0; nb < 4; nb++)
            offB[nb] = (uint32_t)((nb * 16 + (lane & 15)) * KO_PITCH + (lane >> 4) * 16);

        float acc[8][4];
#pragma unroll
        for (int nb = 0; nb < 8; nb++)
#pragma unroll
            for (int q = 0; q < 4; q++) acc[nb][q] = 0.f;

#pragma unroll
        for (int ks = 0; ks < 8; ks++) {
            const uint32_t ko = ks * 32;
            uint32_t ah[4];
            ldsm4(ah, aA + offA + ko);
#pragma unroll
            for (int nb = 0; nb < 4; nb++) {
                uint32_t bh[4];
                ldsm4(bh, aW + offB[nb] + ko);
                mma_f16(acc[nb * 2 + 0], ah, bh[0], bh[2]);
                mma_f16(acc[nb * 2 + 1], ah, bh[1], bh[3]);
            }
        }

        const int brow = wid4 * 16 + (lane >> 2);
#pragma unroll
        for (int nb = 0; nb < 8; nb++) {
            const int o = nb * 8 + (lane & 3) * 2;
            const float2 bias = *(const float2*)&sbias[o];
            float2 v0 = {acc[nb][0] + bias.x, acc[nb][1] + bias.y};
            float2 v1 = {acc[nb][2] + bias.x, acc[nb][3] + bias.y};
            *(float2*)&out[((size_t)brow * N_NODES + n) * CO + o] = v0;
            *(float2*)&out[((size_t)(brow + 8) * N_NODES + n) * CO + o] = v1;
        }
        return;
    }

    if (blockIdx.x >= 1024) {
        // =================== wgen (producer) ===================
        const int wb = blockIdx.x - 1024;
        const int p0 = (wb & 7) * 1024;
        const int n0 = (wb >> 3) * 32;
        float* sE = (float*)smem;      // [32][EMB]

        for (int s = tid; s < 32 * EMB; s += 256)
            sE[s] = E[n0 * EMB + s];

        const int p = p0 + tid * 4;
        float4 w[EMB];
#pragma unroll
        for (int d = 0; d < EMB; d++) w[d] = *(const float4*)&g_Wpp[(size_t)d * 8192 + p];
        __syncthreads();

#pragma unroll 4
        for (int nn = 0; nn < 32; nn++) {
            float4 acc = {0.f, 0.f, 0.f, 0.f};
#pragma unroll
            for (int d = 0; d < EMB; d++) {
                const float e = sE[nn * EMB + d];
                acc.x = fmaf(e, w[d].x, acc.x);
                acc.y = fmaf(e, w[d].y, acc.y);
                acc.z = fmaf(e, w[d].z, acc.z);
                acc.w = fmaf(e, w[d].w, acc.w);
            }
            uint2 pk;
            pk.x = h2_bits(acc.x, acc.y);
            pk.y = h2_bits(acc.z, acc.w);
            *(uint2*)&g_Wt[(size_t)(n0 + nn) * 8192 + p] = pk;
        }
        __threadfence();
        __syncthreads();
        if (tid == 0) atomicAdd(&g_wdone[wb >> 3], 1);
        return;
    }

    // =================== diffusion mma tile (producer) ===================
    const uint32_t sb = smem_u32(smem);
    const int wid = tid >> 5;
    const int lane = tid & 31;
    const int wm = wid >> 1;
    const int wn = wid & 1;
    const int n0 = (blockIdx.x >> 5) * 128;
    const int j0 = (blockIdx.x & 31) * 128;

    int grow[4], gseg[4];
    uint32_t sdst[4];
#pragma unroll
    for (int i = 0; i < 4; i++) {
        const int s = tid + i * 256;
        grow[i] = s >> 3;
        gseg[i] = s & 7;
        sdst[i] = (uint32_t)(grow[i] * ROWB + gseg[i] * 16);
    }

    uint32_t offA[2], offB[4];
#pragma unroll
    for (int mb = 0; mb < 2; mb++)
        offA[mb] = (uint32_t)((wm * 32 + mb * 16 + (lane & 15)) * ROWB + (lane >> 4) * 16);
#pragma unroll
    for (int nb = 0; nb < 4; nb++)
        offB[nb] = (uint32_t)((wn * 64 + nb * 16 + (lane & 15)) * ROWB + (lane >> 4) * 16);

    float acc[2][8][4];
#pragma unroll
    for (int mb = 0; mb < 2; mb++)
#pragma unroll
        for (int nb = 0; nb < 8; nb++)
#pragma unroll
            for (int q = 0; q < 4; q++) acc[mb][nb][q] = 0.f;

#pragma unroll
    for (int c = 0; c < 2; c++) {
        const uint32_t st = sb + c * STAGE_B;
        const int m0 = c * KC;
#pragma unroll
        for (int i = 0; i < 4; i++) {
            cp_async16(st + sdst[i],          g_Ah + (size_t)(n0 + grow[i]) * N_NODES + m0 + gseg[i] * 8);
            cp_async16(st + TILE_B + sdst[i], g_Xh + (size_t)(j0 + grow[i]) * N_NODES + m0 + gseg[i] * 8);
        }
        CP_COMMIT();
    }

    int scur = 0, sld = 2;
    for (int t = 0; t < NT; t++) {
        if (t < NT - 1) { CP_WAIT(1); } else { CP_WAIT(0); }
        __syncthreads();

        if (t + 2 < NT) {
            const uint32_t st = sb + sld * STAGE_B;
            const int m0 = (t + 2) * KC;
#pragma unroll
            for (int i = 0; i < 4; i++) {
                cp_async16(st + sdst[i],          g_Ah + (size_t)(n0 + grow[i]) * N_NODES + m0 + gseg[i] * 8);
                cp_async16(st + TILE_B + sdst[i], g_Xh + (size_t)(j0 + grow[i]) * N_NODES + m0 + gseg[i] * 8);
            }
            CP_COMMIT();
        }

        const uint32_t bA = sb + scur * STAGE_B;
        const uint32_t bB = bA + TILE_B;
#pragma unroll
        for (int ks = 0; ks < 4; ks++) {
            const uint32_t ko = ks * 32;
            uint32_t ah[2][4];
#pragma unroll
            for (int mb = 0; mb < 2; mb++) ldsm4(ah[mb], bA + offA[mb] + ko);
#pragma unroll
            for (int nb = 0; nb < 4; nb++) {
                uint32_t bh[4];
                ldsm4(bh, bB + offB[nb] + ko);
#pragma unroll
                for (int mb = 0; mb < 2; mb++) {
                    mma_f16(acc[mb][nb * 2 + 0], ah[mb], bh[0], bh[2]);
                    mma_f16(acc[mb][nb * 2 + 1], ah[mb], bh[1], bh[3]);
                }
            }
        }
        scur = (scur == 2) ? 0 : scur + 1;
        sld = (sld == 2) ? 0 : sld + 1;
    }

    const int b = (j0 + wn * 64) >> 6;
#pragma unroll
    for (int mb = 0; mb < 2; mb++) {
        const int nrow = n0 + wm * 32 + mb * 16 + (lane >> 2);
#pragma unroll
        for (int nb = 0; nb < 8; nb++) {
            const int c = nb * 8 + (lane & 3) * 2;
            const uint32_t v0 = h2_bits(acc[mb][nb][0], acc[mb][nb][1]);
            const uint32_t v1 = h2_bits(acc[mb][nb][2], acc[mb][nb][3]);
            *(uint32_t*)&g_y1h[((size_t)b * N_NODES + nrow) * CI + c] = v0;
            *(uint32_t*)&g_y1h[((size_t)b * N_NODES + nrow + 8) * CI + c] = v1;
        }
    }
    __threadfence();
    __syncthreads();
    if (tid == 0) atomicAdd(&g_rowdone[blockIdx.x >> 5], 1);
}

// ---------------------------------------------------------------------------
extern "C" void kernel_launch(void* const* d_in, const int* in_sizes, int n_in,
                              void* d_out, int out_size) {
    const float* x  = (const float*)d_in[0];
    const float* E  = (const float*)d_in[1];
    const float* Wp = (const float*)d_in[2];
    const float* bp = (const float*)d_in[3];
    float* out = (float*)d_out;

    cudaFuncSetAttribute(k_main, cudaFuncAttributeMaxDynamicSharedMemorySize, SMEM_MMA);

    k_prep<<<PREP_GRID, 256>>>(x, E, Wp);
    k_main<<<4096, 256, SMEM_MMA>>>(E, bp, out);
}